// round 5
// baseline (speedup 1.0000x reference)
#include <cuda_runtime.h>
#include <cuda_bf16.h>

// EdgeDecoder: per-edge bilinear scores over 5 relations + softmax-expected rating.
//   z_user  [100000, 64] f32
//   z_movie [ 50000, 64] f32
//   rel_emb [     5, 64] f32
//   edge_label_index [2, E] int (32 or 64 — detected at runtime)
//   out [E] f32
//
// R5 (back to the R3 shape — 8 lanes/edge, 4 edges/warp, lowest instr/edge):
//  - LINE-ALIGNED lane mapping: lane sub handles floats [4sub..4sub+3] and
//    [32+4sub..+3], so each gather LDG.128 covers exactly one 128B line per
//    edge-group -> 4 full wavefronts/edge instead of 8 half ones.
//  - index software pipeline: next iteration's (s,d) prefetched before the
//    current edge's compute, hiding idx->gather latency.
//  - softmax shift trick retained (relD[r]=rel[r+1]-rel[0], score'[0]=0).

constexpr int H = 64;

__device__ int   g_idx_is64;
__device__ float g_relD[4 * H];   // rel[r+1][h] - rel[0][h]

__global__ void prep_kernel(const float* __restrict__ rel_emb,
                            const void* __restrict__ edge_idx) {
    const int t = threadIdx.x;
    if (t < 4 * H) {
        const int r = t >> 6, h = t & 63;
        g_relD[t] = rel_emb[(r + 1) * H + h] - rel_emb[h];
    }
    if (t == 0) {
        // int64-vs-int32 index detection: true int64 indices are all in
        // [0, 50000). int32 data reinterpreted as int64 gives lo + hi*2^32
        // with hi ~ U[0,50000): passing all 8 checks is ~impossible.
        const long long* p = (const long long*)edge_idx;
        int is64 = 1;
        #pragma unroll
        for (int i = 0; i < 8; i++) {
            long long v = p[i];
            if (v < 0 || v >= 50000) is64 = 0;
        }
        g_idx_is64 = is64;
    }
}

__global__ __launch_bounds__(256) void edge_decoder_kernel(
    const float* __restrict__ z_user,
    const float* __restrict__ z_movie,
    const void* __restrict__ edge_idx,
    float* __restrict__ out,
    int E)
{
    const int tid     = blockIdx.x * blockDim.x + threadIdx.x;
    const int sub     = threadIdx.x & 7;                 // lane within 8-lane group
    const int ngroups = (gridDim.x * blockDim.x) >> 3;   // total edge groups
    const int g0      = tid >> 3;

    // relD slices, line-aligned mapping: floats [4sub..4sub+3] and [32+4sub..+3].
    // Loaded ONCE per thread; 32 registers.
    float4 rd0[4], rd1[4];
    #pragma unroll
    for (int r = 0; r < 4; r++) {
        rd0[r] = *reinterpret_cast<const float4*>(g_relD + r * H + 4 * sub);
        rd1[r] = *reinterpret_cast<const float4*>(g_relD + r * H + 32 + 4 * sub);
    }

    const int is64 = g_idx_is64;
    const long long* p64 = (const long long*)edge_idx;
    const int*       p32 = (const int*)edge_idx;

    // ---- software pipeline: prime indices for the first edge ----
    int e = g0;
    long long s = 0, d = 0;
    if (e < E) {
        if (is64) { s = __ldg(p64 + e); d = __ldg(p64 + (long long)E + e); }
        else      { s = __ldg(p32 + e); d = __ldg(p32 + E + e); }
    }

    while (e < E) {
        const int en = e + ngroups;

        // issue gathers for the CURRENT edge immediately (line-aligned halves)
        const float* us = z_user  + s * H + 4 * sub;
        const float* ms = z_movie + d * H + 4 * sub;
        const float4 zs0 = *reinterpret_cast<const float4*>(us);
        const float4 zd0 = *reinterpret_cast<const float4*>(ms);
        const float4 zs1 = *reinterpret_cast<const float4*>(us + 32);
        const float4 zd1 = *reinterpret_cast<const float4*>(ms + 32);

        // prefetch NEXT edge's indices while gathers are in flight
        if (en < E) {
            if (is64) { s = __ldg(p64 + en); d = __ldg(p64 + (long long)E + en); }
            else      { s = __ldg(p32 + en); d = __ldg(p32 + E + en); }
        }

        const float q0 = zs0.x * zd0.x;
        const float q1 = zs0.y * zd0.y;
        const float q2 = zs0.z * zd0.z;
        const float q3 = zs0.w * zd0.w;
        const float q4 = zs1.x * zd1.x;
        const float q5 = zs1.y * zd1.y;
        const float q6 = zs1.z * zd1.z;
        const float q7 = zs1.w * zd1.w;

        float sc[4];
        #pragma unroll
        for (int r = 0; r < 4; r++) {
            float a = fmaf(q0, rd0[r].x, fmaf(q1, rd0[r].y,
                      fmaf(q2, rd0[r].z,      q3 * rd0[r].w)));
            float b = fmaf(q4, rd1[r].x, fmaf(q5, rd1[r].y,
                      fmaf(q6, rd1[r].z,      q7 * rd1[r].w)));
            sc[r] = a + b;
        }

        // Butterfly reduce across the 8-lane group (xor offsets stay in-group).
        #pragma unroll
        for (int off = 4; off >= 1; off >>= 1)
            #pragma unroll
            for (int r = 0; r < 4; r++)
                sc[r] += __shfl_xor_sync(0xffffffffu, sc[r], off);

        if (sub == 0) {
            // score'[0] = 0, score'[r+1] = sc[r]
            float m = 0.f;
            #pragma unroll
            for (int r = 0; r < 4; r++) m = fmaxf(m, sc[r]);
            float den = __expf(-m);     // label-0 term
            float num = 0.f;
            #pragma unroll
            for (int r = 0; r < 4; r++) {
                const float ex = __expf(sc[r] - m);
                den += ex;
                num = fmaf(ex, (float)(r + 1), num);
            }
            out[e] = num / den;
        }

        e = en;
    }
}

extern "C" void kernel_launch(void* const* d_in, const int* in_sizes, int n_in,
                              void* d_out, int out_size) {
    const float* z_user  = (const float*)d_in[0];
    const float* z_movie = (const float*)d_in[1];
    const float* rel_emb = (const float*)d_in[2];
    const void*  eidx    = d_in[3];
    float* out = (float*)d_out;

    const int E = out_size;  // one rating per edge

    prep_kernel<<<1, 256>>>(rel_emb, eidx);

    // Persistent-ish grid-stride: 8 CTAs/SM nominal on 152 SMs.
    const int threads = 256;
    const int blocks  = 152 * 8;
    edge_decoder_kernel<<<blocks, threads>>>(z_user, z_movie, eidx, out, E);
}

// round 6
// speedup vs baseline: 1.5068x; 1.5068x over previous
#include <cuda_runtime.h>
#include <cuda_bf16.h>

// EdgeDecoder: per-edge bilinear scores over 5 relations + softmax-expected rating.
//   z_user  [100000, 64] f32
//   z_movie [ 50000, 64] f32
//   rel_emb [     5, 64] f32
//   edge_label_index [2, E] int (32 or 64 — detected at runtime)
//   out [E] f32
//
// R6 = R3 (best: 57.4us) + ONLY the verified-good pieces of R5:
//  - line-aligned lane mapping: lane sub reads floats [4sub..4sub+3] and
//    [32+4sub..+3] so each gather LDG.128 maps to exactly one 128B line
//    per 8-lane group (4 full wavefronts/edge; R5 measured L1 63.9->52.9%).
//  - 32-bit row-offset arithmetic (max offset 25.6MB fits int32).
//  - REVERTED: R5's while-loop software pipeline (it inflated issued
//    instructions ~1.7x). Back to the simple for-loop body.
//  - softmax shift trick retained (relD[r]=rel[r+1]-rel[0], score'[0]=0).

constexpr int H = 64;

__device__ int   g_idx_is64;
__device__ float g_relD[4 * H];   // rel[r+1][h] - rel[0][h]

__global__ void prep_kernel(const float* __restrict__ rel_emb,
                            const void* __restrict__ edge_idx) {
    const int t = threadIdx.x;
    if (t < 4 * H) {
        const int r = t >> 6, h = t & 63;
        g_relD[t] = rel_emb[(r + 1) * H + h] - rel_emb[h];
    }
    if (t == 0) {
        // int64-vs-int32 index detection: true int64 indices are all in
        // [0, 50000). int32 data reinterpreted as int64 gives lo + hi*2^32
        // with hi ~ U[0,50000): passing all 8 checks is ~impossible.
        const long long* p = (const long long*)edge_idx;
        int is64 = 1;
        #pragma unroll
        for (int i = 0; i < 8; i++) {
            long long v = p[i];
            if (v < 0 || v >= 50000) is64 = 0;
        }
        g_idx_is64 = is64;
    }
}

__global__ __launch_bounds__(256) void edge_decoder_kernel(
    const float* __restrict__ z_user,
    const float* __restrict__ z_movie,
    const void* __restrict__ edge_idx,
    float* __restrict__ out,
    int E)
{
    const int tid     = blockIdx.x * blockDim.x + threadIdx.x;
    const int sub     = threadIdx.x & 7;                 // lane within 8-lane group
    const int ngroups = (gridDim.x * blockDim.x) >> 3;   // total edge groups
    const int g0      = tid >> 3;

    // relD slices, line-aligned mapping. Loaded ONCE per thread (32 regs).
    float4 rd0[4], rd1[4];
    #pragma unroll
    for (int r = 0; r < 4; r++) {
        rd0[r] = *reinterpret_cast<const float4*>(g_relD + r * H + 4 * sub);
        rd1[r] = *reinterpret_cast<const float4*>(g_relD + r * H + 32 + 4 * sub);
    }

    const int is64 = g_idx_is64;
    const long long* p64 = (const long long*)edge_idx;
    const int*       p32 = (const int*)edge_idx;

    for (int e = g0; e < E; e += ngroups) {
        int s, d;
        if (is64) {
            s = (int)__ldg(p64 + e);
            d = (int)__ldg(p64 + (long long)E + e);
        } else {
            s = __ldg(p32 + e);
            d = __ldg(p32 + E + e);
        }

        // line-aligned gathers: lane sub covers [4sub..4sub+3] and [32+4sub..+3]
        const float* us = z_user  + s * H;
        const float* ms = z_movie + d * H;
        const float4 zs0 = *reinterpret_cast<const float4*>(us + 4 * sub);
        const float4 zd0 = *reinterpret_cast<const float4*>(ms + 4 * sub);
        const float4 zs1 = *reinterpret_cast<const float4*>(us + 32 + 4 * sub);
        const float4 zd1 = *reinterpret_cast<const float4*>(ms + 32 + 4 * sub);

        const float q0 = zs0.x * zd0.x;
        const float q1 = zs0.y * zd0.y;
        const float q2 = zs0.z * zd0.z;
        const float q3 = zs0.w * zd0.w;
        const float q4 = zs1.x * zd1.x;
        const float q5 = zs1.y * zd1.y;
        const float q6 = zs1.z * zd1.z;
        const float q7 = zs1.w * zd1.w;

        float sc[4];
        #pragma unroll
        for (int r = 0; r < 4; r++) {
            float a = fmaf(q0, rd0[r].x, fmaf(q1, rd0[r].y,
                      fmaf(q2, rd0[r].z,      q3 * rd0[r].w)));
            float b = fmaf(q4, rd1[r].x, fmaf(q5, rd1[r].y,
                      fmaf(q6, rd1[r].z,      q7 * rd1[r].w)));
            sc[r] = a + b;
        }

        // Butterfly reduce across the 8-lane group (xor offsets stay in-group).
        #pragma unroll
        for (int off = 4; off >= 1; off >>= 1)
            #pragma unroll
            for (int r = 0; r < 4; r++)
                sc[r] += __shfl_xor_sync(0xffffffffu, sc[r], off);

        if (sub == 0) {
            // score'[0] = 0, score'[r+1] = sc[r]
            float m = 0.f;
            #pragma unroll
            for (int r = 0; r < 4; r++) m = fmaxf(m, sc[r]);
            float den = __expf(-m);     // label-0 term
            float num = 0.f;
            #pragma unroll
            for (int r = 0; r < 4; r++) {
                const float ex = __expf(sc[r] - m);
                den += ex;
                num = fmaf(ex, (float)(r + 1), num);
            }
            out[e] = num / den;
        }
    }
}

extern "C" void kernel_launch(void* const* d_in, const int* in_sizes, int n_in,
                              void* d_out, int out_size) {
    const float* z_user  = (const float*)d_in[0];
    const float* z_movie = (const float*)d_in[1];
    const float* rel_emb = (const float*)d_in[2];
    const void*  eidx    = d_in[3];
    float* out = (float*)d_out;

    const int E = out_size;  // one rating per edge

    prep_kernel<<<1, 256>>>(rel_emb, eidx);

    // Persistent-ish grid-stride: 8 CTAs/SM nominal on 152 SMs.
    const int threads = 256;
    const int blocks  = 152 * 8;
    edge_decoder_kernel<<<blocks, threads>>>(z_user, z_movie, eidx, out, E);
}

// round 7
// speedup vs baseline: 1.5761x; 1.0460x over previous
#include <cuda_runtime.h>
#include <cuda_bf16.h>

// EdgeDecoder: per-edge bilinear scores over 5 relations + softmax-expected rating.
//   z_user  [100000, 64] f32
//   z_movie [ 50000, 64] f32
//   rel_emb [     5, 64] f32
//   edge_label_index [2, E] int (32 or 64 — detected at runtime)
//   out [E] f32
//
// R7 = R6 (best: 56.1us) + MLP/occupancy push (profile showed nothing
// saturated: L1 43.5%, issue 55%, occ 48.4% with regs=62 -> 4 CTAs/SM):
//  - relD moved to SHARED memory (1KB): frees 32 regs -> more CTAs/SM.
//    LDS.128 broadcast is conflict-free; loaded with short liveness right
//    before the score FMAs.
//  - 2-edge unroll in the 8-lane layout: all 8 gather float4s issued before
//    any consumption -> 4 outstanding 128B gathers per warp (2x MLP).
//  - line-aligned lane mapping + softmax shift trick retained.

constexpr int H = 64;

__device__ int   g_idx_is64;
__device__ float g_relD[4 * H];   // rel[r+1][h] - rel[0][h]

__global__ void prep_kernel(const float* __restrict__ rel_emb,
                            const void* __restrict__ edge_idx) {
    const int t = threadIdx.x;
    if (t < 4 * H) {
        const int r = t >> 6, h = t & 63;
        g_relD[t] = rel_emb[(r + 1) * H + h] - rel_emb[h];
    }
    if (t == 0) {
        // int64-vs-int32 index detection: true int64 indices are all in
        // [0, 50000). int32 data reinterpreted as int64 gives lo + hi*2^32
        // with hi ~ U[0,50000): passing all 8 checks is ~impossible.
        const long long* p = (const long long*)edge_idx;
        int is64 = 1;
        #pragma unroll
        for (int i = 0; i < 8; i++) {
            long long v = p[i];
            if (v < 0 || v >= 50000) is64 = 0;
        }
        g_idx_is64 = is64;
    }
}

__device__ __forceinline__ float softmax_expect(const float sc[4]) {
    // score'[0] = 0, score'[r+1] = sc[r]
    float m = 0.f;
    #pragma unroll
    for (int r = 0; r < 4; r++) m = fmaxf(m, sc[r]);
    float den = __expf(-m);     // label-0 term
    float num = 0.f;
    #pragma unroll
    for (int r = 0; r < 4; r++) {
        const float ex = __expf(sc[r] - m);
        den += ex;
        num = fmaf(ex, (float)(r + 1), num);
    }
    return num / den;
}

__global__ __launch_bounds__(256) void edge_decoder_kernel(
    const float* __restrict__ z_user,
    const float* __restrict__ z_movie,
    const void* __restrict__ edge_idx,
    float* __restrict__ out,
    int E)
{
    __shared__ float s_rel[4 * H];
    for (int t = threadIdx.x; t < 4 * H; t += 256)
        s_rel[t] = g_relD[t];
    __syncthreads();

    const int tid     = blockIdx.x * blockDim.x + threadIdx.x;
    const int sub     = threadIdx.x & 7;                 // lane within 8-lane group
    const int ngroups = (gridDim.x * blockDim.x) >> 3;   // total edge groups
    const int g0      = tid >> 3;

    const int is64 = g_idx_is64;
    const long long* p64 = (const long long*)edge_idx;
    const int*       p32 = (const int*)edge_idx;

    const float* rel_lo = s_rel + 4 * sub;        // floats [4sub..4sub+3]
    const float* rel_hi = s_rel + 32 + 4 * sub;   // floats [32+4sub..+3]

    for (int e = g0; e < E; e += 2 * ngroups) {
        const int  e2   = e + ngroups;
        const bool has2 = (e2 < E);

        // ---- issue ALL loads up front: 2 index pairs, then 8 gather float4s
        int sA, dA, sB = 0, dB = 0;
        if (is64) {
            sA = (int)__ldg(p64 + e);
            dA = (int)__ldg(p64 + (long long)E + e);
            if (has2) { sB = (int)__ldg(p64 + e2); dB = (int)__ldg(p64 + (long long)E + e2); }
        } else {
            sA = __ldg(p32 + e);
            dA = __ldg(p32 + E + e);
            if (has2) { sB = __ldg(p32 + e2); dB = __ldg(p32 + E + e2); }
        }

        const float* uA = z_user  + sA * H;
        const float* mA = z_movie + dA * H;
        const float* uB = z_user  + sB * H;   // idx 0 when !has2 (safe)
        const float* mB = z_movie + dB * H;

        const float4 zsA0 = *reinterpret_cast<const float4*>(uA + 4 * sub);
        const float4 zdA0 = *reinterpret_cast<const float4*>(mA + 4 * sub);
        const float4 zsA1 = *reinterpret_cast<const float4*>(uA + 32 + 4 * sub);
        const float4 zdA1 = *reinterpret_cast<const float4*>(mA + 32 + 4 * sub);
        const float4 zsB0 = *reinterpret_cast<const float4*>(uB + 4 * sub);
        const float4 zdB0 = *reinterpret_cast<const float4*>(mB + 4 * sub);
        const float4 zsB1 = *reinterpret_cast<const float4*>(uB + 32 + 4 * sub);
        const float4 zdB1 = *reinterpret_cast<const float4*>(mB + 32 + 4 * sub);

        // ---- elementwise products
        const float a0 = zsA0.x * zdA0.x, a1 = zsA0.y * zdA0.y,
                    a2 = zsA0.z * zdA0.z, a3 = zsA0.w * zdA0.w;
        const float a4 = zsA1.x * zdA1.x, a5 = zsA1.y * zdA1.y,
                    a6 = zsA1.z * zdA1.z, a7 = zsA1.w * zdA1.w;
        const float b0 = zsB0.x * zdB0.x, b1 = zsB0.y * zdB0.y,
                    b2 = zsB0.z * zdB0.z, b3 = zsB0.w * zdB0.w;
        const float b4 = zsB1.x * zdB1.x, b5 = zsB1.y * zdB1.y,
                    b6 = zsB1.z * zdB1.z, b7 = zsB1.w * zdB1.w;

        // ---- scores: relD read from smem with short liveness, shared by A & B
        float scA[4], scB[4];
        #pragma unroll
        for (int r = 0; r < 4; r++) {
            const float4 r0 = *reinterpret_cast<const float4*>(rel_lo + r * H);
            const float4 r1 = *reinterpret_cast<const float4*>(rel_hi + r * H);
            scA[r] = fmaf(a0, r0.x, fmaf(a1, r0.y, fmaf(a2, r0.z, a3 * r0.w)))
                   + fmaf(a4, r1.x, fmaf(a5, r1.y, fmaf(a6, r1.z, a7 * r1.w)));
            scB[r] = fmaf(b0, r0.x, fmaf(b1, r0.y, fmaf(b2, r0.z, b3 * r0.w)))
                   + fmaf(b4, r1.x, fmaf(b5, r1.y, fmaf(b6, r1.z, b7 * r1.w)));
        }

        // ---- butterfly reduce across the 8-lane group
        #pragma unroll
        for (int off = 4; off >= 1; off >>= 1) {
            #pragma unroll
            for (int r = 0; r < 4; r++) {
                scA[r] += __shfl_xor_sync(0xffffffffu, scA[r], off);
                scB[r] += __shfl_xor_sync(0xffffffffu, scB[r], off);
            }
        }

        if (sub == 0) {
            out[e] = softmax_expect(scA);
            if (has2) out[e2] = softmax_expect(scB);
        }
    }
}

extern "C" void kernel_launch(void* const* d_in, const int* in_sizes, int n_in,
                              void* d_out, int out_size) {
    const float* z_user  = (const float*)d_in[0];
    const float* z_movie = (const float*)d_in[1];
    const float* rel_emb = (const float*)d_in[2];
    const void*  eidx    = d_in[3];
    float* out = (float*)d_out;

    const int E = out_size;  // one rating per edge

    prep_kernel<<<1, 256>>>(rel_emb, eidx);

    // Persistent-ish grid-stride: 8 CTAs/SM nominal on 152 SMs.
    const int threads = 256;
    const int blocks  = 152 * 8;
    edge_decoder_kernel<<<blocks, threads>>>(z_user, z_movie, eidx, out, E);
}